// round 2
// baseline (speedup 1.0000x reference)
#include <cuda_runtime.h>
#include <cuda_bf16.h>
#include <math.h>

// Problem constants (fixed by the dataset)
#define NN 8192
#define EE 65536
#define F_IN 512
#define H1D 4096
#define H2D 1024
#define F_OUT 10

// ---------------- scratch (device globals: allocation-free) ----------------
__device__ int   g_is64;          // 1 if edge_index is int64, 0 if int32
__device__ float g_deg[NN];
__device__ float g_dinv[NN];
__device__ int   g_src[EE];
__device__ int   g_dst[EE];
__device__ float g_norm[EE];
__device__ float g_aggx[(size_t)NN * F_IN];    // 16 MB : A @ x
__device__ float g_h1[(size_t)NN * H1D];       // 128 MB: relu((A x) W1 + b1)
__device__ float g_t2[(size_t)NN * H2D];       // 32 MB : h1 @ W2
__device__ float g_h2[(size_t)NN * H2D];       // 32 MB : relu(A t2 + b2)
__device__ float g_t3[(size_t)NN * F_OUT];     // h2 @ W3
__device__ float g_a3[(size_t)NN * F_OUT];     // A t3

// ---------------- dtype probe ----------------
// If the buffer is int32 (two indices per int64 read), a 64-bit read is
// >= 2^32 whenever the high half is a nonzero index -> out of [0, NN).
__global__ void k_detect(const void* __restrict__ ei) {
    if (threadIdx.x == 0 && blockIdx.x == 0) {
        const long long* p = (const long long*)ei;
        int ok64 = 1;
        for (int i = 0; i < 64; i++) {
            long long v = p[i];
            if (v < 0 || v >= NN) { ok64 = 0; break; }
        }
        g_is64 = ok64;
    }
}

__device__ __forceinline__ int edge_val(const void* ei, int idx) {
    if (g_is64) return (int)((const long long*)ei)[idx];
    return ((const int*)ei)[idx];
}

// ---------------- graph preprocessing ----------------
__global__ void k_deg_init() {
    int i = blockIdx.x * blockDim.x + threadIdx.x;
    if (i < NN) g_deg[i] = 1.0f;  // self-loop
}

__global__ void k_deg_count(const void* __restrict__ ei) {
    int e = blockIdx.x * blockDim.x + threadIdx.x;
    if (e < EE) {
        int d = edge_val(ei, EE + e);
        atomicAdd(&g_deg[d], 1.0f);
    }
}

__global__ void k_dinv() {
    int i = blockIdx.x * blockDim.x + threadIdx.x;
    if (i < NN) g_dinv[i] = rsqrtf(g_deg[i]);
}

__global__ void k_edge_prep(const void* __restrict__ ei) {
    int e = blockIdx.x * blockDim.x + threadIdx.x;
    if (e < EE) {
        int s = edge_val(ei, e);
        int d = edge_val(ei, EE + e);
        g_src[e] = s;
        g_dst[e] = d;
        g_norm[e] = g_dinv[s] * g_dinv[d];
    }
}

// ---------------- aggregation (A @ H) ----------------
// self-loop init: out[i,:] = dinv[i]^2 * in[i,:]     (vectorized, F4 = F/4)
__global__ void k_selfinit4(const float* __restrict__ in, float* __restrict__ out, int F4) {
    int idx = blockIdx.x * blockDim.x + threadIdx.x;
    int total = NN * F4;
    if (idx >= total) return;
    int row = idx / F4;
    float s = g_dinv[row];
    s = s * s;
    float4 v = ((const float4*)in)[idx];
    v.x *= s; v.y *= s; v.z *= s; v.w *= s;
    ((float4*)out)[idx] = v;
}

// edge scatter: out[dst,:] += norm * in[src,:]
__global__ void k_scatter4(const float* __restrict__ in, float* __restrict__ out, int F4) {
    int idx = blockIdx.x * blockDim.x + threadIdx.x;
    int total = EE * F4;
    if (idx >= total) return;
    int e = idx / F4;
    int f = idx - e * F4;
    int s = g_src[e], d = g_dst[e];
    float nrm = g_norm[e];
    float4 v = ((const float4*)in)[s * F4 + f];
    float* o = out + ((size_t)d * F4 + f) * 4;
    atomicAdd(o + 0, v.x * nrm);
    atomicAdd(o + 1, v.y * nrm);
    atomicAdd(o + 2, v.z * nrm);
    atomicAdd(o + 3, v.w * nrm);
}

// scalar versions for F=10
__global__ void k_selfinit_s(const float* __restrict__ in, float* __restrict__ out) {
    int idx = blockIdx.x * blockDim.x + threadIdx.x;
    if (idx >= NN * F_OUT) return;
    int row = idx / F_OUT;
    float s = g_dinv[row];
    out[idx] = s * s * in[idx];
}

__global__ void k_scatter_s(const float* __restrict__ in, float* __restrict__ out) {
    int idx = blockIdx.x * blockDim.x + threadIdx.x;
    if (idx >= EE * F_OUT) return;
    int e = idx / F_OUT;
    int f = idx - e * F_OUT;
    atomicAdd(&out[g_dst[e] * F_OUT + f], g_norm[e] * in[g_src[e] * F_OUT + f]);
}

// ---------------- dense GEMM: C = A(MxK) * B(KxN)  [+ bias, relu] ----------------
// 128x128 block tile, 8 k-slice, 8x8 per-thread, 256 threads.
template<bool BIAS_RELU>
__global__ __launch_bounds__(256, 2)
void sgemm128(const float* __restrict__ A, const float* __restrict__ B,
              const float* __restrict__ bias, float* __restrict__ C,
              int M, int N, int K) {
    __shared__ float As[8][128];
    __shared__ float Bs[8][128];
    const int tid = threadIdx.x;
    const int bm = blockIdx.y * 128;
    const int bn = blockIdx.x * 128;

    const int arow = tid >> 1;            // 0..127
    const int acol = (tid & 1) * 4;       // 0 or 4
    const int brow = tid >> 5;            // 0..7
    const int bcol = (tid & 31) * 4;      // 0..124

    const float* Ag = A + (size_t)(bm + arow) * K + acol;
    const float* Bg = B + (size_t)brow * N + bn + bcol;

    const int tx = tid & 15;
    const int ty = tid >> 4;

    float acc[8][8];
#pragma unroll
    for (int i = 0; i < 8; i++)
#pragma unroll
        for (int j = 0; j < 8; j++) acc[i][j] = 0.0f;

    for (int k0 = 0; k0 < K; k0 += 8) {
        float4 av = *(const float4*)(Ag + k0);
        float4 bv = *(const float4*)(Bg + (size_t)k0 * N);
        As[acol + 0][arow] = av.x;
        As[acol + 1][arow] = av.y;
        As[acol + 2][arow] = av.z;
        As[acol + 3][arow] = av.w;
        *(float4*)&Bs[brow][bcol] = bv;
        __syncthreads();

#pragma unroll
        for (int k = 0; k < 8; k++) {
            float a[8], b[8];
            *(float4*)(a)     = *(const float4*)&As[k][ty * 8];
            *(float4*)(a + 4) = *(const float4*)&As[k][ty * 8 + 4];
            *(float4*)(b)     = *(const float4*)&Bs[k][tx * 8];
            *(float4*)(b + 4) = *(const float4*)&Bs[k][tx * 8 + 4];
#pragma unroll
            for (int i = 0; i < 8; i++)
#pragma unroll
                for (int j = 0; j < 8; j++) acc[i][j] = fmaf(a[i], b[j], acc[i][j]);
        }
        __syncthreads();
    }

    // epilogue
#pragma unroll
    for (int i = 0; i < 8; i++) {
        int row = bm + ty * 8 + i;
        float* c = C + (size_t)row * N + bn + tx * 8;
        float out[8];
#pragma unroll
        for (int j = 0; j < 8; j++) {
            float v = acc[i][j];
            if (BIAS_RELU) {
                v += bias[bn + tx * 8 + j];
                v = fmaxf(v, 0.0f);
            }
            out[j] = v;
        }
        *(float4*)(c)     = *(float4*)(out);
        *(float4*)(c + 4) = *(float4*)(out + 4);
    }
}

// bias + relu in place (layer 2, after aggregation)
__global__ void k_bias_relu(float* __restrict__ h, const float* __restrict__ bias, int F) {
    int idx = blockIdx.x * blockDim.x + threadIdx.x;
    if (idx >= NN * F) return;
    int col = idx % F;
    h[idx] = fmaxf(h[idx] + bias[col], 0.0f);
}

// small GEMM: C[NN,10] = A[NN,1024] @ B[1024,10]; W3 staged in smem
__global__ void sgemm_small(const float* __restrict__ A, const float* __restrict__ B,
                            float* __restrict__ C) {
    __shared__ float Ws[H2D * F_OUT];  // 40 KB
    int tid = threadIdx.y * F_OUT + threadIdx.x;
    for (int i = tid; i < H2D * F_OUT; i += F_OUT * 16) Ws[i] = B[i];
    __syncthreads();
    int m = blockIdx.x * 16 + threadIdx.y;
    int n = threadIdx.x;
    const float4* a = (const float4*)(A + (size_t)m * H2D);
    float s = 0.0f;
#pragma unroll 8
    for (int k4 = 0; k4 < H2D / 4; k4++) {
        float4 v = a[k4];
        int k = k4 * 4;
        s += v.x * Ws[(k + 0) * F_OUT + n];
        s += v.y * Ws[(k + 1) * F_OUT + n];
        s += v.z * Ws[(k + 2) * F_OUT + n];
        s += v.w * Ws[(k + 3) * F_OUT + n];
    }
    C[m * F_OUT + n] = s;
}

// final: out = log_softmax(a3 + b3), one thread per row
__global__ void k_logsoftmax(const float* __restrict__ a3, const float* __restrict__ b3,
                             float* __restrict__ out) {
    int m = blockIdx.x * blockDim.x + threadIdx.x;
    if (m >= NN) return;
    float v[F_OUT];
    float mx = -1e30f;
#pragma unroll
    for (int n = 0; n < F_OUT; n++) {
        v[n] = a3[m * F_OUT + n] + b3[n];
        mx = fmaxf(mx, v[n]);
    }
    float s = 0.0f;
#pragma unroll
    for (int n = 0; n < F_OUT; n++) s += expf(v[n] - mx);
    float lse = mx + logf(s);
#pragma unroll
    for (int n = 0; n < F_OUT; n++) out[m * F_OUT + n] = v[n] - lse;
}

// ---------------- launch ----------------
extern "C" void kernel_launch(void* const* d_in, const int* in_sizes, int n_in,
                              void* d_out, int out_size) {
    const float* x  = (const float*)d_in[0];
    const float* W1 = (const float*)d_in[1];
    const float* b1 = (const float*)d_in[2];
    const float* W2 = (const float*)d_in[3];
    const float* b2 = (const float*)d_in[4];
    const float* W3 = (const float*)d_in[5];
    const float* b3 = (const float*)d_in[6];
    const void*  ei = d_in[7];
    float* out = (float*)d_out;

    float *aggx, *h1, *t2, *h2, *t3, *a3;
    cudaGetSymbolAddress((void**)&aggx, g_aggx);
    cudaGetSymbolAddress((void**)&h1,   g_h1);
    cudaGetSymbolAddress((void**)&t2,   g_t2);
    cudaGetSymbolAddress((void**)&h2,   g_h2);
    cudaGetSymbolAddress((void**)&t3,   g_t3);
    cudaGetSymbolAddress((void**)&a3,   g_a3);

    // graph preprocessing (dtype-robust)
    k_detect<<<1, 32>>>(ei);
    k_deg_init<<<(NN + 255) / 256, 256>>>();
    k_deg_count<<<(EE + 255) / 256, 256>>>(ei);
    k_dinv<<<(NN + 255) / 256, 256>>>();
    k_edge_prep<<<(EE + 255) / 256, 256>>>(ei);

    // ---- layer 1: aggregate x (F=512) first, then GEMM with fused bias+relu
    {
        int F4 = F_IN / 4;
        k_selfinit4<<<(NN * F4 + 255) / 256, 256>>>(x, aggx, F4);
        k_scatter4<<<(EE * F4 + 255) / 256, 256>>>(x, aggx, F4);
        dim3 grid(H1D / 128, NN / 128);
        sgemm128<true><<<grid, 256>>>(aggx, W1, b1, h1, NN, H1D, F_IN);
    }

    // ---- layer 2: GEMM first (4096 -> 1024), then aggregate, then bias+relu
    {
        dim3 grid(H2D / 128, NN / 128);
        sgemm128<false><<<grid, 256>>>(h1, W2, nullptr, t2, NN, H2D, H1D);
        int F4 = H2D / 4;
        k_selfinit4<<<(NN * F4 + 255) / 256, 256>>>(t2, h2, F4);
        k_scatter4<<<(EE * F4 + 255) / 256, 256>>>(t2, h2, F4);
        k_bias_relu<<<(NN * H2D + 255) / 256, 256>>>(h2, b2, H2D);
    }

    // ---- layer 3: small GEMM (1024 -> 10), aggregate, bias + log_softmax
    {
        dim3 blk(F_OUT, 16);
        sgemm_small<<<NN / 16, blk>>>(h2, W3, t3);
        k_selfinit_s<<<(NN * F_OUT + 255) / 256, 256>>>(t3, a3);
        k_scatter_s<<<(EE * F_OUT + 255) / 256, 256>>>(t3, a3);
        k_logsoftmax<<<(NN + 255) / 256, 256>>>(a3, b3, out);
    }
}

// round 3
// speedup vs baseline: 2.4124x; 2.4124x over previous
#include <cuda_runtime.h>
#include <cuda_bf16.h>
#include <math.h>
#include <stdint.h>

// Problem constants (fixed by the dataset)
#define NN 8192
#define EE 65536
#define F_IN 512
#define H1D 4096
#define H2D 1024
#define F_OUT 10

// ---------------- scratch (device globals: allocation-free) ----------------
__device__ int   g_is64;          // 1 if edge_index is int64, 0 if int32
__device__ float g_deg[NN];
__device__ float g_dinv[NN];
__device__ int   g_src[EE];
__device__ int   g_dst[EE];
__device__ float g_norm[EE];
__device__ float g_aggx[(size_t)NN * F_IN];    // 16 MB : A @ x
__device__ float g_h1[(size_t)NN * H1D];       // 128 MB: relu((A x) W1 + b1)
__device__ float g_t2[(size_t)NN * H2D];       // 32 MB : h1 @ W2
__device__ float g_h2[(size_t)NN * H2D];       // 32 MB : relu(A t2 + b2)
__device__ float g_t3[(size_t)NN * F_OUT];     // h2 @ W3
__device__ float g_a3[(size_t)NN * F_OUT];     // A t3

// ---------------- dtype probe ----------------
__global__ void k_detect(const void* __restrict__ ei) {
    if (threadIdx.x == 0 && blockIdx.x == 0) {
        const long long* p = (const long long*)ei;
        int ok64 = 1;
        for (int i = 0; i < 64; i++) {
            long long v = p[i];
            if (v < 0 || v >= NN) { ok64 = 0; break; }
        }
        g_is64 = ok64;
    }
}

__device__ __forceinline__ int edge_val(const void* ei, int idx) {
    if (g_is64) return (int)((const long long*)ei)[idx];
    return ((const int*)ei)[idx];
}

// ---------------- graph preprocessing ----------------
__global__ void k_deg_init() {
    int i = blockIdx.x * blockDim.x + threadIdx.x;
    if (i < NN) g_deg[i] = 1.0f;  // self-loop
}

__global__ void k_deg_count(const void* __restrict__ ei) {
    int e = blockIdx.x * blockDim.x + threadIdx.x;
    if (e < EE) atomicAdd(&g_deg[edge_val(ei, EE + e)], 1.0f);
}

__global__ void k_dinv() {
    int i = blockIdx.x * blockDim.x + threadIdx.x;
    if (i < NN) g_dinv[i] = rsqrtf(g_deg[i]);
}

__global__ void k_edge_prep(const void* __restrict__ ei) {
    int e = blockIdx.x * blockDim.x + threadIdx.x;
    if (e < EE) {
        int s = edge_val(ei, e);
        int d = edge_val(ei, EE + e);
        g_src[e] = s;
        g_dst[e] = d;
        g_norm[e] = g_dinv[s] * g_dinv[d];
    }
}

// ---------------- aggregation (A @ H) ----------------
__global__ void k_selfinit4(const float* __restrict__ in, float* __restrict__ out, int F4) {
    int idx = blockIdx.x * blockDim.x + threadIdx.x;
    int total = NN * F4;
    if (idx >= total) return;
    int row = idx / F4;
    float s = g_dinv[row];
    s = s * s;
    float4 v = ((const float4*)in)[idx];
    v.x *= s; v.y *= s; v.z *= s; v.w *= s;
    ((float4*)out)[idx] = v;
}

__global__ void k_scatter4(const float* __restrict__ in, float* __restrict__ out, int F4) {
    int idx = blockIdx.x * blockDim.x + threadIdx.x;
    int total = EE * F4;
    if (idx >= total) return;
    int e = idx / F4;
    int f = idx - e * F4;
    int s = g_src[e], d = g_dst[e];
    float nrm = g_norm[e];
    float4 v = ((const float4*)in)[s * F4 + f];
    float* o = out + ((size_t)d * F4 + f) * 4;
    atomicAdd(o + 0, v.x * nrm);
    atomicAdd(o + 1, v.y * nrm);
    atomicAdd(o + 2, v.z * nrm);
    atomicAdd(o + 3, v.w * nrm);
}

__global__ void k_selfinit_s(const float* __restrict__ in, float* __restrict__ out) {
    int idx = blockIdx.x * blockDim.x + threadIdx.x;
    if (idx >= NN * F_OUT) return;
    int row = idx / F_OUT;
    float s = g_dinv[row];
    out[idx] = s * s * in[idx];
}

__global__ void k_scatter_s(const float* __restrict__ in, float* __restrict__ out) {
    int idx = blockIdx.x * blockDim.x + threadIdx.x;
    if (idx >= EE * F_OUT) return;
    int e = idx / F_OUT;
    int f = idx - e * F_OUT;
    atomicAdd(&out[g_dst[e] * F_OUT + f], g_norm[e] * in[g_src[e] * F_OUT + f]);
}

// ---------------- TF32 tensor-core GEMM ----------------
// C[M,N] = A[M,K] @ B[K,N], both row-major fp32 in GMEM, TF32 mma, fp32 acc.
// Block tile 128x128, K-step 32, 256 threads = 8 warps in 2(M) x 4(N).
// Warp tile 64x32 = 4x4 m16n8k8 tiles.

#define A_LD 36               // 32 + 4 pad (floats)
#define B_LD 136              // 128 + 8 pad (floats)
#define A_SZ (128 * A_LD)     // 4608 floats / stage
#define B_SZ (32 * B_LD)      // 4352 floats / stage
#define SMEM_FLOATS (2 * A_SZ + 2 * B_SZ)   // 17920 floats = 71680 B

__device__ __forceinline__ uint32_t f2tf32(float f) {
    uint32_t u;
    asm("cvt.rna.tf32.f32 %0, %1;" : "=r"(u) : "f"(f));
    return u;
}

__device__ __forceinline__ void mma_tf32(float c[4],
                                         uint32_t a0, uint32_t a1, uint32_t a2, uint32_t a3,
                                         uint32_t b0, uint32_t b1) {
    asm volatile(
        "mma.sync.aligned.m16n8k8.row.col.f32.tf32.tf32.f32 "
        "{%0,%1,%2,%3}, {%4,%5,%6,%7}, {%8,%9}, {%0,%1,%2,%3};"
        : "+f"(c[0]), "+f"(c[1]), "+f"(c[2]), "+f"(c[3])
        : "r"(a0), "r"(a1), "r"(a2), "r"(a3), "r"(b0), "r"(b1));
}

template<bool BIAS_RELU>
__global__ __launch_bounds__(256, 1)
void tgemm(const float* __restrict__ A, const float* __restrict__ B,
           const float* __restrict__ bias, float* __restrict__ C,
           int M, int N, int K) {
    extern __shared__ float sm[];
    float* As = sm;                // [2][128][A_LD]
    float* Bs = sm + 2 * A_SZ;     // [2][32][B_LD]

    const int tid  = threadIdx.x;
    const int lane = tid & 31;
    const int w    = tid >> 5;
    const int wm   = w >> 2;       // 0..1
    const int wn   = w & 3;        // 0..3
    const int bm   = blockIdx.y * 128;
    const int bn   = blockIdx.x * 128;

    // per-thread global load mapping
    const int am  = tid >> 3;          // A row within tile block of 32 rows step (idx>>3)
    const int ak4 = tid & 7;           // A float4-col (0..7)
    const int bk  = tid >> 5;          // B k-row base (idx>>5)
    const int bn4 = tid & 31;          // B float4-col (0..31)

    float acc[4][4][4];
#pragma unroll
    for (int i = 0; i < 4; i++)
#pragma unroll
        for (int j = 0; j < 4; j++)
#pragma unroll
            for (int r = 0; r < 4; r++) acc[i][j][r] = 0.0f;

    float4 ra[4], rb[4];

    // prefetch tile k0 = 0
#pragma unroll
    for (int i = 0; i < 4; i++) {
        int m = am + i * 32;                       // (tid + i*256) >> 3
        ra[i] = *(const float4*)(A + (size_t)(bm + m) * K + ak4 * 4);
        int kb = bk + i * 8;                       // (tid + i*256) >> 5
        rb[i] = *(const float4*)(B + (size_t)kb * N + bn + bn4 * 4);
    }
    // stage 0 store (with tf32 conversion)
    {
#pragma unroll
        for (int i = 0; i < 4; i++) {
            int m = am + i * 32;
            uint32_t* pa = (uint32_t*)&As[m * A_LD + ak4 * 4];
            pa[0] = f2tf32(ra[i].x); pa[1] = f2tf32(ra[i].y);
            pa[2] = f2tf32(ra[i].z); pa[3] = f2tf32(ra[i].w);
            int kb = bk + i * 8;
            uint32_t* pb = (uint32_t*)&Bs[kb * B_LD + bn4 * 4];
            pb[0] = f2tf32(rb[i].x); pb[1] = f2tf32(rb[i].y);
            pb[2] = f2tf32(rb[i].z); pb[3] = f2tf32(rb[i].w);
        }
    }
    __syncthreads();

    int st = 0;
    for (int k0 = 32; k0 <= K; k0 += 32) {
        const bool has_next = (k0 < K);
        if (has_next) {
#pragma unroll
            for (int i = 0; i < 4; i++) {
                int m = am + i * 32;
                ra[i] = *(const float4*)(A + (size_t)(bm + m) * K + k0 + ak4 * 4);
                int kb = bk + i * 8;
                rb[i] = *(const float4*)(B + (size_t)(k0 + kb) * N + bn + bn4 * 4);
            }
        }

        // compute on stage st
        const uint32_t* Au = (const uint32_t*)(As + st * A_SZ);
        const uint32_t* Bu = (const uint32_t*)(Bs + st * B_SZ);
        const int r4 = lane >> 2;      // 0..7
        const int c4 = lane & 3;       // 0..3
#pragma unroll
        for (int kk = 0; kk < 4; kk++) {
            const int kb = kk * 8;
            uint32_t af[4][4];
#pragma unroll
            for (int mt = 0; mt < 4; mt++) {
                const int mrow = wm * 64 + mt * 16 + r4;
                af[mt][0] = Au[(mrow    ) * A_LD + kb + c4    ];
                af[mt][1] = Au[(mrow + 8) * A_LD + kb + c4    ];
                af[mt][2] = Au[(mrow    ) * A_LD + kb + c4 + 4];
                af[mt][3] = Au[(mrow + 8) * A_LD + kb + c4 + 4];
            }
            uint32_t bf[4][2];
#pragma unroll
            for (int nt = 0; nt < 4; nt++) {
                const int ncol = wn * 32 + nt * 8 + r4;
                bf[nt][0] = Bu[(kb + c4    ) * B_LD + ncol];
                bf[nt][1] = Bu[(kb + c4 + 4) * B_LD + ncol];
            }
#pragma unroll
            for (int mt = 0; mt < 4; mt++)
#pragma unroll
                for (int nt = 0; nt < 4; nt++)
                    mma_tf32(acc[mt][nt], af[mt][0], af[mt][1], af[mt][2], af[mt][3],
                             bf[nt][0], bf[nt][1]);
        }

        if (has_next) {
            float* Ad = As + (st ^ 1) * A_SZ;
            float* Bd = Bs + (st ^ 1) * B_SZ;
#pragma unroll
            for (int i = 0; i < 4; i++) {
                int m = am + i * 32;
                uint32_t* pa = (uint32_t*)&Ad[m * A_LD + ak4 * 4];
                pa[0] = f2tf32(ra[i].x); pa[1] = f2tf32(ra[i].y);
                pa[2] = f2tf32(ra[i].z); pa[3] = f2tf32(ra[i].w);
                int kb = bk + i * 8;
                uint32_t* pb = (uint32_t*)&Bd[kb * B_LD + bn4 * 4];
                pb[0] = f2tf32(rb[i].x); pb[1] = f2tf32(rb[i].y);
                pb[2] = f2tf32(rb[i].z); pb[3] = f2tf32(rb[i].w);
            }
        }
        __syncthreads();
        st ^= 1;
    }

    // epilogue: float2 stores; lanes in a quad cover 32 contiguous bytes
    const int r4 = lane >> 2;
    const int c2 = (lane & 3) * 2;
#pragma unroll
    for (int mt = 0; mt < 4; mt++) {
#pragma unroll
        for (int nt = 0; nt < 4; nt++) {
            int row = bm + wm * 64 + mt * 16 + r4;
            int col = bn + wn * 32 + nt * 8 + c2;
            float v0 = acc[mt][nt][0], v1 = acc[mt][nt][1];
            float v2 = acc[mt][nt][2], v3 = acc[mt][nt][3];
            if (BIAS_RELU) {
                float bb0 = bias[col], bb1 = bias[col + 1];
                v0 = fmaxf(v0 + bb0, 0.0f); v1 = fmaxf(v1 + bb1, 0.0f);
                v2 = fmaxf(v2 + bb0, 0.0f); v3 = fmaxf(v3 + bb1, 0.0f);
            }
            float2 p01 = make_float2(v0, v1);
            float2 p23 = make_float2(v2, v3);
            *(float2*)&C[(size_t)row * N + col]       = p01;
            *(float2*)&C[(size_t)(row + 8) * N + col] = p23;
        }
    }
}

// bias + relu in place (layer 2, after aggregation)
__global__ void k_bias_relu(float* __restrict__ h, const float* __restrict__ bias, int F) {
    int idx = blockIdx.x * blockDim.x + threadIdx.x;
    if (idx >= NN * F) return;
    int col = idx % F;
    h[idx] = fmaxf(h[idx] + bias[col], 0.0f);
}

// small GEMM: C[NN,10] = A[NN,1024] @ B[1024,10]; W3 staged in smem
__global__ void sgemm_small(const float* __restrict__ A, const float* __restrict__ B,
                            float* __restrict__ C) {
    __shared__ float Ws[H2D * F_OUT];  // 40 KB
    int tid = threadIdx.y * F_OUT + threadIdx.x;
    for (int i = tid; i < H2D * F_OUT; i += F_OUT * 16) Ws[i] = B[i];
    __syncthreads();
    int m = blockIdx.x * 16 + threadIdx.y;
    int n = threadIdx.x;
    const float4* a = (const float4*)(A + (size_t)m * H2D);
    float s = 0.0f;
#pragma unroll 8
    for (int k4 = 0; k4 < H2D / 4; k4++) {
        float4 v = a[k4];
        int k = k4 * 4;
        s += v.x * Ws[(k + 0) * F_OUT + n];
        s += v.y * Ws[(k + 1) * F_OUT + n];
        s += v.z * Ws[(k + 2) * F_OUT + n];
        s += v.w * Ws[(k + 3) * F_OUT + n];
    }
    C[m * F_OUT + n] = s;
}

// final: out = log_softmax(a3 + b3)
__global__ void k_logsoftmax(const float* __restrict__ a3, const float* __restrict__ b3,
                             float* __restrict__ out) {
    int m = blockIdx.x * blockDim.x + threadIdx.x;
    if (m >= NN) return;
    float v[F_OUT];
    float mx = -1e30f;
#pragma unroll
    for (int n = 0; n < F_OUT; n++) {
        v[n] = a3[m * F_OUT + n] + b3[n];
        mx = fmaxf(mx, v[n]);
    }
    float s = 0.0f;
#pragma unroll
    for (int n = 0; n < F_OUT; n++) s += expf(v[n] - mx);
    float lse = mx + logf(s);
#pragma unroll
    for (int n = 0; n < F_OUT; n++) out[m * F_OUT + n] = v[n] - lse;
}

// ---------------- launch ----------------
extern "C" void kernel_launch(void* const* d_in, const int* in_sizes, int n_in,
                              void* d_out, int out_size) {
    const float* x  = (const float*)d_in[0];
    const float* W1 = (const float*)d_in[1];
    const float* b1 = (const float*)d_in[2];
    const float* W2 = (const float*)d_in[3];
    const float* b2 = (const float*)d_in[4];
    const float* W3 = (const float*)d_in[5];
    const float* b3 = (const float*)d_in[6];
    const void*  ei = d_in[7];
    float* out = (float*)d_out;

    float *aggx, *h1, *t2, *h2, *t3, *a3;
    cudaGetSymbolAddress((void**)&aggx, g_aggx);
    cudaGetSymbolAddress((void**)&h1,   g_h1);
    cudaGetSymbolAddress((void**)&t2,   g_t2);
    cudaGetSymbolAddress((void**)&h2,   g_h2);
    cudaGetSymbolAddress((void**)&t3,   g_t3);
    cudaGetSymbolAddress((void**)&a3,   g_a3);

    const int smem_bytes = SMEM_FLOATS * 4;   // 71680
    cudaFuncSetAttribute(tgemm<true>,  cudaFuncAttributeMaxDynamicSharedMemorySize, smem_bytes);
    cudaFuncSetAttribute(tgemm<false>, cudaFuncAttributeMaxDynamicSharedMemorySize, smem_bytes);

    // graph preprocessing (dtype-robust)
    k_detect<<<1, 32>>>(ei);
    k_deg_init<<<(NN + 255) / 256, 256>>>();
    k_deg_count<<<(EE + 255) / 256, 256>>>(ei);
    k_dinv<<<(NN + 255) / 256, 256>>>();
    k_edge_prep<<<(EE + 255) / 256, 256>>>(ei);

    // ---- layer 1: aggregate x (F=512) first, then tensor-core GEMM + bias/relu
    {
        int F4 = F_IN / 4;
        k_selfinit4<<<(NN * F4 + 255) / 256, 256>>>(x, aggx, F4);
        k_scatter4<<<(EE * F4 + 255) / 256, 256>>>(x, aggx, F4);
        dim3 grid(H1D / 128, NN / 128);
        tgemm<true><<<grid, 256, smem_bytes>>>(aggx, W1, b1, h1, NN, H1D, F_IN);
    }

    // ---- layer 2: GEMM first (4096 -> 1024), then aggregate, then bias+relu
    {
        dim3 grid(H2D / 128, NN / 128);
        tgemm<false><<<grid, 256, smem_bytes>>>(h1, W2, nullptr, t2, NN, H2D, H1D);
        int F4 = H2D / 4;
        k_selfinit4<<<(NN * F4 + 255) / 256, 256>>>(t2, h2, F4);
        k_scatter4<<<(EE * F4 + 255) / 256, 256>>>(t2, h2, F4);
        k_bias_relu<<<(NN * H2D + 255) / 256, 256>>>(h2, b2, H2D);
    }

    // ---- layer 3: small GEMM (1024 -> 10), aggregate, bias + log_softmax
    {
        dim3 blk(F_OUT, 16);
        sgemm_small<<<NN / 16, blk>>>(h2, W3, t3);
        k_selfinit_s<<<(NN * F_OUT + 255) / 256, 256>>>(t3, a3);
        k_scatter_s<<<(EE * F_OUT + 255) / 256, 256>>>(t3, a3);
        k_logsoftmax<<<(NN + 255) / 256, 256>>>(a3, b3, out);
    }
}

// round 4
// speedup vs baseline: 3.3467x; 1.3873x over previous
#include <cuda_runtime.h>
#include <cuda_fp16.h>
#include <cuda_bf16.h>
#include <math.h>
#include <stdint.h>

// Problem constants (fixed by the dataset)
#define NN 8192
#define EE 65536
#define F_IN 512
#define H1D 4096
#define H2D 1024
#define F_OUT 10

// ---------------- scratch (device globals: allocation-free) ----------------
__device__ int    g_is64;
__device__ float  g_deg[NN];
__device__ float  g_dinv[NN];
__device__ int    g_src[EE];
__device__ int    g_dst[EE];
__device__ float  g_norm[EE];
__device__ float  g_aggx[(size_t)NN * F_IN];     // 16 MB : A @ x (fp32, atomics)
__device__ __half g_aggxh[(size_t)NN * F_IN];    // 8 MB  : fp16 copy
__device__ __half g_w1t[(size_t)H1D * F_IN];     // 4 MB  : W1^T fp16 [4096][512]
__device__ __half g_w2t[(size_t)H2D * H1D];      // 8 MB  : W2^T fp16 [1024][4096]
__device__ __half g_h1h[(size_t)NN * H1D];       // 64 MB : relu((A x) W1 + b1) fp16
__device__ float  g_t2[(size_t)NN * H2D];        // 32 MB : h1 @ W2
__device__ float  g_h2[(size_t)NN * H2D];        // 32 MB : relu(A t2 + b2)
__device__ float  g_t3[(size_t)NN * F_OUT];
__device__ float  g_a3[(size_t)NN * F_OUT];

// ---------------- dtype probe ----------------
__global__ void k_detect(const void* __restrict__ ei) {
    if (threadIdx.x == 0 && blockIdx.x == 0) {
        const long long* p = (const long long*)ei;
        int ok64 = 1;
        for (int i = 0; i < 64; i++) {
            long long v = p[i];
            if (v < 0 || v >= NN) { ok64 = 0; break; }
        }
        g_is64 = ok64;
    }
}

__device__ __forceinline__ int edge_val(const void* ei, int idx) {
    if (g_is64) return (int)((const long long*)ei)[idx];
    return ((const int*)ei)[idx];
}

// ---------------- graph preprocessing ----------------
__global__ void k_deg_init() {
    int i = blockIdx.x * blockDim.x + threadIdx.x;
    if (i < NN) g_deg[i] = 1.0f;
}

__global__ void k_deg_count(const void* __restrict__ ei) {
    int e = blockIdx.x * blockDim.x + threadIdx.x;
    if (e < EE) atomicAdd(&g_deg[edge_val(ei, EE + e)], 1.0f);
}

__global__ void k_dinv() {
    int i = blockIdx.x * blockDim.x + threadIdx.x;
    if (i < NN) g_dinv[i] = rsqrtf(g_deg[i]);
}

__global__ void k_edge_prep(const void* __restrict__ ei) {
    int e = blockIdx.x * blockDim.x + threadIdx.x;
    if (e < EE) {
        int s = edge_val(ei, e);
        int d = edge_val(ei, EE + e);
        g_src[e] = s;
        g_dst[e] = d;
        g_norm[e] = g_dinv[s] * g_dinv[d];
    }
}

// ---------------- aggregation (A @ H) ----------------
__global__ void k_selfinit4(const float* __restrict__ in, float* __restrict__ out, int F4) {
    int idx = blockIdx.x * blockDim.x + threadIdx.x;
    int total = NN * F4;
    if (idx >= total) return;
    int row = idx / F4;
    float s = g_dinv[row];
    s = s * s;
    float4 v = ((const float4*)in)[idx];
    v.x *= s; v.y *= s; v.z *= s; v.w *= s;
    ((float4*)out)[idx] = v;
}

__global__ void k_scatter4(const float* __restrict__ in, float* __restrict__ out, int F4) {
    int idx = blockIdx.x * blockDim.x + threadIdx.x;
    int total = EE * F4;
    if (idx >= total) return;
    int e = idx / F4;
    int f = idx - e * F4;
    int s = g_src[e], d = g_dst[e];
    float nrm = g_norm[e];
    float4 v = ((const float4*)in)[s * F4 + f];
    float* o = out + ((size_t)d * F4 + f) * 4;
    atomicAdd(o + 0, v.x * nrm);
    atomicAdd(o + 1, v.y * nrm);
    atomicAdd(o + 2, v.z * nrm);
    atomicAdd(o + 3, v.w * nrm);
}

__global__ void k_selfinit_s(const float* __restrict__ in, float* __restrict__ out) {
    int idx = blockIdx.x * blockDim.x + threadIdx.x;
    if (idx >= NN * F_OUT) return;
    int row = idx / F_OUT;
    float s = g_dinv[row];
    out[idx] = s * s * in[idx];
}

__global__ void k_scatter_s(const float* __restrict__ in, float* __restrict__ out) {
    int idx = blockIdx.x * blockDim.x + threadIdx.x;
    if (idx >= EE * F_OUT) return;
    int e = idx / F_OUT;
    int f = idx - e * F_OUT;
    atomicAdd(&out[g_dst[e] * F_OUT + f], g_norm[e] * in[g_src[e] * F_OUT + f]);
}

// ---------------- fp32 -> fp16 convert (vectorized) ----------------
__global__ void k_f2h(const float* __restrict__ in, __half* __restrict__ out, int total4) {
    int idx = blockIdx.x * blockDim.x + threadIdx.x;
    if (idx >= total4) return;
    float4 v = ((const float4*)in)[idx];
    __half2 h0 = __floats2half2_rn(v.x, v.y);
    __half2 h1 = __floats2half2_rn(v.z, v.w);
    uint2 p;
    p.x = *(uint32_t*)&h0;
    p.y = *(uint32_t*)&h1;
    ((uint2*)out)[idx] = p;
}

// ---------------- transpose + convert: in[R][C] fp32 -> out[C][R] fp16 ----------------
__global__ void k_transpose_h(const float* __restrict__ in, __half* __restrict__ out,
                              int R, int C) {
    __shared__ float t[32][33];
    int c0 = blockIdx.x * 32, r0 = blockIdx.y * 32;
#pragma unroll
    for (int i = threadIdx.y; i < 32; i += 8)
        t[i][threadIdx.x] = in[(size_t)(r0 + i) * C + c0 + threadIdx.x];
    __syncthreads();
#pragma unroll
    for (int i = threadIdx.y; i < 32; i += 8)
        out[(size_t)(c0 + i) * R + r0 + threadIdx.x] = __float2half(t[threadIdx.x][i]);
}

// ---------------- FP16 tensor-core GEMM ----------------
// C[M,N] = A[M,K] @ B[N,K]^T : A fp16 [M][K] k-contiguous, B fp16 [N][K] k-contiguous.
// Block tile 128(M) x 128(N), K-step 32, 256 threads = 8 warps in 2(M) x 4(N).
// Warp tile 64x32 = 4x4 m16n8k16 tiles, 2 k-subtiles per stage.

#define HLD 40                     // halves per smem row (32 + 8 pad)
#define HSTAGE (128 * HLD)         // halves per stage per operand

__device__ __forceinline__ void mma_f16(float c[4], uint32_t a0, uint32_t a1,
                                        uint32_t a2, uint32_t a3,
                                        uint32_t b0, uint32_t b1) {
    asm volatile(
        "mma.sync.aligned.m16n8k16.row.col.f32.f16.f16.f32 "
        "{%0,%1,%2,%3}, {%4,%5,%6,%7}, {%8,%9}, {%0,%1,%2,%3};"
        : "+f"(c[0]), "+f"(c[1]), "+f"(c[2]), "+f"(c[3])
        : "r"(a0), "r"(a1), "r"(a2), "r"(a3), "r"(b0), "r"(b1));
}

template<bool BIAS_RELU, bool OUT_HALF>
__global__ __launch_bounds__(256, 1)
void hgemm(const __half* __restrict__ A, const __half* __restrict__ B,
           const float* __restrict__ bias, void* __restrict__ Cv,
           int M, int N, int K) {
    extern __shared__ __half smh[];
    __half* As = smh;                    // [2][128][HLD]
    __half* Bs = smh + 2 * HSTAGE;       // [2][128][HLD]

    const int tid  = threadIdx.x;
    const int lane = tid & 31;
    const int w    = tid >> 5;
    const int wm   = w >> 2;             // 0..1
    const int wn   = w & 3;              // 0..3
    const int bm   = blockIdx.y * 128;
    const int bn   = blockIdx.x * 128;

    // global load mapping: 512 chunks of 8 halves (16B); thread covers chunk tid, tid+256
    const int r0 = tid >> 2;             // row of chunk 0 (0..63)
    const int kc = tid & 3;              // 8-half group (0..3)

    float acc[4][4][4];
#pragma unroll
    for (int i = 0; i < 4; i++)
#pragma unroll
        for (int j = 0; j < 4; j++)
#pragma unroll
            for (int r = 0; r < 4; r++) acc[i][j][r] = 0.0f;

    uint4 ra[2], rb[2];

    // prefetch stage 0
#pragma unroll
    for (int i = 0; i < 2; i++) {
        int row = r0 + i * 64;
        ra[i] = *(const uint4*)(A + (size_t)(bm + row) * K + kc * 8);
        rb[i] = *(const uint4*)(B + (size_t)(bn + row) * K + kc * 8);
    }
#pragma unroll
    for (int i = 0; i < 2; i++) {
        int row = r0 + i * 64;
        *(uint4*)&As[row * HLD + kc * 8] = ra[i];
        *(uint4*)&Bs[row * HLD + kc * 8] = rb[i];
    }
    __syncthreads();

    const int g = lane >> 2;             // 0..7
    const int t = lane & 3;              // 0..3

    int st = 0;
    for (int k0 = 32; k0 <= K; k0 += 32) {
        const bool has_next = (k0 < K);
        if (has_next) {
#pragma unroll
            for (int i = 0; i < 2; i++) {
                int row = r0 + i * 64;
                ra[i] = *(const uint4*)(A + (size_t)(bm + row) * K + k0 + kc * 8);
                rb[i] = *(const uint4*)(B + (size_t)(bn + row) * K + k0 + kc * 8);
            }
        }

        const __half* Ac = As + st * HSTAGE;
        const __half* Bc = Bs + st * HSTAGE;
#pragma unroll
        for (int kk = 0; kk < 2; kk++) {
            const int kb = kk * 16 + 2 * t;
            uint32_t af[4][4];
#pragma unroll
            for (int mt = 0; mt < 4; mt++) {
                const int mrow = wm * 64 + mt * 16 + g;
                af[mt][0] = *(const uint32_t*)&Ac[(mrow    ) * HLD + kb    ];
                af[mt][1] = *(const uint32_t*)&Ac[(mrow + 8) * HLD + kb    ];
                af[mt][2] = *(const uint32_t*)&Ac[(mrow    ) * HLD + kb + 8];
                af[mt][3] = *(const uint32_t*)&Ac[(mrow + 8) * HLD + kb + 8];
            }
            uint32_t bf[4][2];
#pragma unroll
            for (int nt = 0; nt < 4; nt++) {
                const int nrow = wn * 32 + nt * 8 + g;
                bf[nt][0] = *(const uint32_t*)&Bc[nrow * HLD + kb    ];
                bf[nt][1] = *(const uint32_t*)&Bc[nrow * HLD + kb + 8];
            }
#pragma unroll
            for (int mt = 0; mt < 4; mt++)
#pragma unroll
                for (int nt = 0; nt < 4; nt++)
                    mma_f16(acc[mt][nt], af[mt][0], af[mt][1], af[mt][2], af[mt][3],
                            bf[nt][0], bf[nt][1]);
        }

        if (has_next) {
            __half* Ad = As + (st ^ 1) * HSTAGE;
            __half* Bd = Bs + (st ^ 1) * HSTAGE;
#pragma unroll
            for (int i = 0; i < 2; i++) {
                int row = r0 + i * 64;
                *(uint4*)&Ad[row * HLD + kc * 8] = ra[i];
                *(uint4*)&Bd[row * HLD + kc * 8] = rb[i];
            }
        }
        __syncthreads();
        st ^= 1;
    }

    // epilogue
    const int c2 = t * 2;
#pragma unroll
    for (int mt = 0; mt < 4; mt++) {
#pragma unroll
        for (int nt = 0; nt < 4; nt++) {
            int row = bm + wm * 64 + mt * 16 + g;
            int col = bn + wn * 32 + nt * 8 + c2;
            float v0 = acc[mt][nt][0], v1 = acc[mt][nt][1];
            float v2 = acc[mt][nt][2], v3 = acc[mt][nt][3];
            if (BIAS_RELU) {
                float bb0 = bias[col], bb1 = bias[col + 1];
                v0 = fmaxf(v0 + bb0, 0.0f); v1 = fmaxf(v1 + bb1, 0.0f);
                v2 = fmaxf(v2 + bb0, 0.0f); v3 = fmaxf(v3 + bb1, 0.0f);
            }
            if (OUT_HALF) {
                __half* C = (__half*)Cv;
                __half2 p01 = __floats2half2_rn(v0, v1);
                __half2 p23 = __floats2half2_rn(v2, v3);
                *(__half2*)&C[(size_t)row * N + col]       = p01;
                *(__half2*)&C[(size_t)(row + 8) * N + col] = p23;
            } else {
                float* C = (float*)Cv;
                *(float2*)&C[(size_t)row * N + col]       = make_float2(v0, v1);
                *(float2*)&C[(size_t)(row + 8) * N + col] = make_float2(v2, v3);
            }
        }
    }
}

// bias + relu in place (layer 2, after aggregation)
__global__ void k_bias_relu(float* __restrict__ h, const float* __restrict__ bias, int F) {
    int idx = blockIdx.x * blockDim.x + threadIdx.x;
    if (idx >= NN * F) return;
    int col = idx % F;
    h[idx] = fmaxf(h[idx] + bias[col], 0.0f);
}

// small GEMM: C[NN,10] = A[NN,1024] @ B[1024,10]; W3 staged in smem
__global__ void sgemm_small(const float* __restrict__ A, const float* __restrict__ B,
                            float* __restrict__ C) {
    __shared__ float Ws[H2D * F_OUT];  // 40 KB
    int tid = threadIdx.y * F_OUT + threadIdx.x;
    for (int i = tid; i < H2D * F_OUT; i += F_OUT * 16) Ws[i] = B[i];
    __syncthreads();
    int m = blockIdx.x * 16 + threadIdx.y;
    int n = threadIdx.x;
    const float4* a = (const float4*)(A + (size_t)m * H2D);
    float s = 0.0f;
#pragma unroll 8
    for (int k4 = 0; k4 < H2D / 4; k4++) {
        float4 v = a[k4];
        int k = k4 * 4;
        s += v.x * Ws[(k + 0) * F_OUT + n];
        s += v.y * Ws[(k + 1) * F_OUT + n];
        s += v.z * Ws[(k + 2) * F_OUT + n];
        s += v.w * Ws[(k + 3) * F_OUT + n];
    }
    C[m * F_OUT + n] = s;
}

// final: out = log_softmax(a3 + b3)
__global__ void k_logsoftmax(const float* __restrict__ a3, const float* __restrict__ b3,
                             float* __restrict__ out) {
    int m = blockIdx.x * blockDim.x + threadIdx.x;
    if (m >= NN) return;
    float v[F_OUT];
    float mx = -1e30f;
#pragma unroll
    for (int n = 0; n < F_OUT; n++) {
        v[n] = a3[m * F_OUT + n] + b3[n];
        mx = fmaxf(mx, v[n]);
    }
    float s = 0.0f;
#pragma unroll
    for (int n = 0; n < F_OUT; n++) s += expf(v[n] - mx);
    float lse = mx + logf(s);
#pragma unroll
    for (int n = 0; n < F_OUT; n++) out[m * F_OUT + n] = v[n] - lse;
}

// ---------------- launch ----------------
extern "C" void kernel_launch(void* const* d_in, const int* in_sizes, int n_in,
                              void* d_out, int out_size) {
    const float* x  = (const float*)d_in[0];
    const float* W1 = (const float*)d_in[1];
    const float* b1 = (const float*)d_in[2];
    const float* W2 = (const float*)d_in[3];
    const float* b2 = (const float*)d_in[4];
    const float* W3 = (const float*)d_in[5];
    const float* b3 = (const float*)d_in[6];
    const void*  ei = d_in[7];
    float* out = (float*)d_out;

    float *aggx, *t2, *h2, *t3, *a3;
    __half *aggxh, *w1t, *w2t, *h1h;
    cudaGetSymbolAddress((void**)&aggx,  g_aggx);
    cudaGetSymbolAddress((void**)&aggxh, g_aggxh);
    cudaGetSymbolAddress((void**)&w1t,   g_w1t);
    cudaGetSymbolAddress((void**)&w2t,   g_w2t);
    cudaGetSymbolAddress((void**)&h1h,   g_h1h);
    cudaGetSymbolAddress((void**)&t2,    g_t2);
    cudaGetSymbolAddress((void**)&h2,    g_h2);
    cudaGetSymbolAddress((void**)&t3,    g_t3);
    cudaGetSymbolAddress((void**)&a3,    g_a3);

    const int smem_bytes = 4 * HSTAGE * 2;   // 40960
    cudaFuncSetAttribute(hgemm<true, true>,   cudaFuncAttributeMaxDynamicSharedMemorySize, smem_bytes);
    cudaFuncSetAttribute(hgemm<false, false>, cudaFuncAttributeMaxDynamicSharedMemorySize, smem_bytes);

    // weight transposes (independent of graph preprocessing)
    {
        dim3 blk(32, 8);
        dim3 g1(H1D / 32, F_IN / 32);
        k_transpose_h<<<g1, blk>>>(W1, w1t, F_IN, H1D);
        dim3 g2(H2D / 32, H1D / 32);
        k_transpose_h<<<g2, blk>>>(W2, w2t, H1D, H2D);
    }

    // graph preprocessing (dtype-robust)
    k_detect<<<1, 32>>>(ei);
    k_deg_init<<<(NN + 255) / 256, 256>>>();
    k_deg_count<<<(EE + 255) / 256, 256>>>(ei);
    k_dinv<<<(NN + 255) / 256, 256>>>();
    k_edge_prep<<<(EE + 255) / 256, 256>>>(ei);

    // ---- layer 1: aggregate x (F=512) in fp32, convert to fp16, GEMM + bias/relu
    {
        int F4 = F_IN / 4;
        k_selfinit4<<<(NN * F4 + 255) / 256, 256>>>(x, aggx, F4);
        k_scatter4<<<(EE * F4 + 255) / 256, 256>>>(x, aggx, F4);
        k_f2h<<<(NN * F4 + 255) / 256, 256>>>(aggx, aggxh, NN * F4);
        dim3 grid(H1D / 128, NN / 128);
        hgemm<true, true><<<grid, 256, smem_bytes>>>(aggxh, w1t, b1, h1h, NN, H1D, F_IN);
    }

    // ---- layer 2: GEMM first (4096 -> 1024), then aggregate, then bias+relu
    {
        dim3 grid(H2D / 128, NN / 128);
        hgemm<false, false><<<grid, 256, smem_bytes>>>(h1h, w2t, nullptr, t2, NN, H2D, H1D);
        int F4 = H2D / 4;
        k_selfinit4<<<(NN * F4 + 255) / 256, 256>>>(t2, h2, F4);
        k_scatter4<<<(EE * F4 + 255) / 256, 256>>>(t2, h2, F4);
        k_bias_relu<<<(NN * H2D + 255) / 256, 256>>>(h2, b2, H2D);
    }

    // ---- layer 3: small GEMM (1024 -> 10), aggregate, bias + log_softmax
    {
        dim3 blk(F_OUT, 16);
        sgemm_small<<<NN / 16, blk>>>(h2, W3, t3);
        k_selfinit_s<<<(NN * F_OUT + 255) / 256, 256>>>(t3, a3);
        k_scatter_s<<<(EE * F_OUT + 255) / 256, 256>>>(t3, a3);
        k_logsoftmax<<<(NN + 255) / 256, 256>>>(a3, b3, out);
    }
}

// round 6
// speedup vs baseline: 5.7019x; 1.7038x over previous
#include <cuda_runtime.h>
#include <cuda_fp16.h>
#include <cuda_bf16.h>
#include <math.h>
#include <stdint.h>

// Problem constants (fixed by the dataset)
#define NN 8192
#define EE 65536
#define F_IN 512
#define H1D 4096
#define H2D 1024
#define F_OUT 10

// ---------------- scratch (device globals: allocation-free) ----------------
__device__ int    g_is64;
__device__ float  g_deg[NN];
__device__ float  g_dinv[NN];
__device__ int    g_src[EE];
__device__ int    g_dst[EE];
__device__ float  g_norm[EE];
__device__ int    g_rowstart[NN + 1];
__device__ int    g_cursor[NN];
__device__ int    g_csrc[EE];
__device__ float  g_cnorm[EE];
__device__ __half g_aggxh[(size_t)NN * F_IN];    // fp16 aggregated x
__device__ __half g_w1t[(size_t)H1D * F_IN];     // W1^T fp16 [4096][512]
__device__ __half g_w2t[(size_t)H2D * H1D];      // W2^T fp16 [1024][4096]
__device__ __half g_h1h[(size_t)NN * H1D];       // layer1 out fp16
__device__ float  g_t2[(size_t)NN * H2D];
__device__ float  g_h2[(size_t)NN * H2D];
__device__ float  g_t3[(size_t)NN * F_OUT];
__device__ float  g_a3[(size_t)NN * F_OUT];

// ---------------- dtype probe ----------------
__global__ void k_detect(const void* __restrict__ ei) {
    if (threadIdx.x == 0 && blockIdx.x == 0) {
        const long long* p = (const long long*)ei;
        int ok64 = 1;
        for (int i = 0; i < 64; i++) {
            long long v = p[i];
            if (v < 0 || v >= NN) { ok64 = 0; break; }
        }
        g_is64 = ok64;
    }
}

__device__ __forceinline__ int edge_val(const void* ei, int idx) {
    if (g_is64) return (int)((const long long*)ei)[idx];
    return ((const int*)ei)[idx];
}

// ---------------- graph preprocessing ----------------
__global__ void k_deg_init() {
    int i = blockIdx.x * blockDim.x + threadIdx.x;
    if (i < NN) g_deg[i] = 1.0f;
}

__global__ void k_deg_count(const void* __restrict__ ei) {
    int e = blockIdx.x * blockDim.x + threadIdx.x;
    if (e < EE) atomicAdd(&g_deg[edge_val(ei, EE + e)], 1.0f);
}

__global__ void k_dinv() {
    int i = blockIdx.x * blockDim.x + threadIdx.x;
    if (i < NN) g_dinv[i] = rsqrtf(g_deg[i]);
}

__global__ void k_edge_prep(const void* __restrict__ ei) {
    int e = blockIdx.x * blockDim.x + threadIdx.x;
    if (e < EE) {
        int s = edge_val(ei, e);
        int d = edge_val(ei, EE + e);
        g_src[e] = s;
        g_dst[e] = d;
        g_norm[e] = g_dinv[s] * g_dinv[d];
    }
}

// exclusive scan of (deg-1) over NN nodes; 1 block, 256 threads, 32 nodes each
__global__ void k_scan() {
    __shared__ int part[256];
    int t = threadIdx.x;
    int base = t * 32;
    int cnt[32];
    int s = 0;
#pragma unroll
    for (int i = 0; i < 32; i++) {
        cnt[i] = (int)g_deg[base + i] - 1;   // edges only (self handled separately)
        s += cnt[i];
    }
    part[t] = s;
    __syncthreads();
    for (int off = 1; off < 256; off <<= 1) {
        int v = (t >= off) ? part[t - off] : 0;
        __syncthreads();
        part[t] += v;
        __syncthreads();
    }
    int run = (t > 0) ? part[t - 1] : 0;
#pragma unroll
    for (int i = 0; i < 32; i++) {
        g_rowstart[base + i] = run;
        g_cursor[base + i] = 0;
        run += cnt[i];
    }
    if (t == 255) g_rowstart[NN] = run;
}

__global__ void k_place() {
    int e = blockIdx.x * blockDim.x + threadIdx.x;
    if (e >= EE) return;
    int d = g_dst[e];
    int pos = g_rowstart[d] + atomicAdd(&g_cursor[d], 1);
    g_csrc[pos]  = g_src[e];
    g_cnorm[pos] = g_norm[e];
}

// ---------------- CSR gather aggregation ----------------
// layer 1: out[r,:] = dinv^2 * x[r,:] + sum norm * x[src,:]   -> fp16 out
__global__ void k_gather1(const float* __restrict__ x, __half* __restrict__ out) {
    const int r = blockIdx.x;
    const int f = threadIdx.x;             // 0..127 (float4 lanes, F=512)
    const int s0 = g_rowstart[r], s1 = g_rowstart[r + 1];
    float di = g_dinv[r];
    float self = di * di;
    float4 v = ((const float4*)x)[(size_t)r * 128 + f];
    float4 acc = make_float4(v.x * self, v.y * self, v.z * self, v.w * self);
    for (int i = s0; i < s1; i++) {
        int src = g_csrc[i];
        float nrm = g_cnorm[i];
        float4 u = ((const float4*)x)[(size_t)src * 128 + f];
        acc.x += nrm * u.x; acc.y += nrm * u.y;
        acc.z += nrm * u.z; acc.w += nrm * u.w;
    }
    __half2 h0 = __floats2half2_rn(acc.x, acc.y);
    __half2 h1 = __floats2half2_rn(acc.z, acc.w);
    uint2 p;
    p.x = *(uint32_t*)&h0;
    p.y = *(uint32_t*)&h1;
    ((uint2*)out)[(size_t)r * 128 + f] = p;
}

// layer 2: out[r,:] = relu( dinv^2*t2[r,:] + sum norm*t2[src,:] + bias )
__global__ void k_gather2(const float* __restrict__ t2, const float* __restrict__ bias,
                          float* __restrict__ out) {
    const int r = blockIdx.x;
    const int f = threadIdx.x;             // 0..255 (float4 lanes, F=1024)
    const int s0 = g_rowstart[r], s1 = g_rowstart[r + 1];
    float di = g_dinv[r];
    float self = di * di;
    float4 v = ((const float4*)t2)[(size_t)r * 256 + f];
    float4 acc = make_float4(v.x * self, v.y * self, v.z * self, v.w * self);
    for (int i = s0; i < s1; i++) {
        int src = g_csrc[i];
        float nrm = g_cnorm[i];
        float4 u = ((const float4*)t2)[(size_t)src * 256 + f];
        acc.x += nrm * u.x; acc.y += nrm * u.y;
        acc.z += nrm * u.z; acc.w += nrm * u.w;
    }
    float4 b = ((const float4*)bias)[f];
    acc.x = fmaxf(acc.x + b.x, 0.0f);
    acc.y = fmaxf(acc.y + b.y, 0.0f);
    acc.z = fmaxf(acc.z + b.z, 0.0f);
    acc.w = fmaxf(acc.w + b.w, 0.0f);
    ((float4*)out)[(size_t)r * 256 + f] = acc;
}

// layer 3: scalar gather at F=10
__global__ void k_gather3(const float* __restrict__ t3, float* __restrict__ out) {
    int idx = blockIdx.x * blockDim.x + threadIdx.x;
    if (idx >= NN * F_OUT) return;
    int r = idx / F_OUT;
    int f = idx - r * F_OUT;
    const int s0 = g_rowstart[r], s1 = g_rowstart[r + 1];
    float di = g_dinv[r];
    float acc = di * di * t3[(size_t)r * F_OUT + f];
    for (int i = s0; i < s1; i++)
        acc += g_cnorm[i] * t3[(size_t)g_csrc[i] * F_OUT + f];
    out[idx] = acc;
}

// ---------------- transpose + convert: in[R][C] fp32 -> out[C][R] fp16 ----------------
__global__ void k_transpose_h(const float* __restrict__ in, __half* __restrict__ out,
                              int R, int C) {
    __shared__ float t[32][33];
    int c0 = blockIdx.x * 32, r0 = blockIdx.y * 32;
#pragma unroll
    for (int i = threadIdx.y; i < 32; i += 8)
        t[i][threadIdx.x] = in[(size_t)(r0 + i) * C + c0 + threadIdx.x];
    __syncthreads();
#pragma unroll
    for (int i = threadIdx.y; i < 32; i += 8)
        out[(size_t)(c0 + i) * R + r0 + threadIdx.x] = __float2half(t[threadIdx.x][i]);
}

// ---------------- FP16 tensor-core GEMM, cp.async 3-stage pipeline ----------------
// C[M,N] = A[M,K] @ B[N,K]^T : A, B fp16 k-contiguous.
// Block 128x128, K-chunk 32, 256 threads = 8 warps (2M x 4N), warp 64x32.

#define HLD 40                         // halves per smem row (32 + 8 pad)
#define HSTAGE (128 * HLD)             // halves per operand per stage (5120)
#define NSTAGE 3
#define GEMM_SMEM (NSTAGE * HSTAGE * 2 * 2)   // bytes = 61440

__device__ __forceinline__ uint32_t smem_u32(const void* p) {
    uint32_t a;
    asm("{ .reg .u64 t; cvta.to.shared.u64 t, %1; cvt.u32.u64 %0, t; }" : "=r"(a) : "l"(p));
    return a;
}

__device__ __forceinline__ void mma_f16(float c[4], uint32_t a0, uint32_t a1,
                                        uint32_t a2, uint32_t a3,
                                        uint32_t b0, uint32_t b1) {
    asm volatile(
        "mma.sync.aligned.m16n8k16.row.col.f32.f16.f16.f32 "
        "{%0,%1,%2,%3}, {%4,%5,%6,%7}, {%8,%9}, {%0,%1,%2,%3};"
        : "+f"(c[0]), "+f"(c[1]), "+f"(c[2]), "+f"(c[3])
        : "r"(a0), "r"(a1), "r"(a2), "r"(a3), "r"(b0), "r"(b1));
}

template<bool BIAS_RELU, bool OUT_HALF>
__global__ __launch_bounds__(256, 2)
void hgemm(const __half* __restrict__ A, const __half* __restrict__ B,
           const float* __restrict__ bias, void* __restrict__ Cv,
           int M, int N, int K) {
    extern __shared__ __half smh[];
    const uint32_t sb = smem_u32(smh);

    const int tid  = threadIdx.x;
    const int lane = tid & 31;
    const int w    = tid >> 5;
    const int wm   = w >> 2;
    const int wn   = w & 3;
    const int bm   = blockIdx.y * 128;
    const int bn   = blockIdx.x * 128;

    // chunk mapping for cp.async: 512 16B-chunks per operand; thread does 2 + 2
    const int r0 = tid >> 2;            // rows 0..63 (and +64)
    const int kc = tid & 3;             // 8-half group

    float acc[4][4][4];
#pragma unroll
    for (int i = 0; i < 4; i++)
#pragma unroll
        for (int j = 0; j < 4; j++)
#pragma unroll
            for (int r = 0; r < 4; r++) acc[i][j][r] = 0.0f;

    const int nch = K >> 5;

    // byte offsets: A stage s at s*HSTAGE*2; B at (NSTAGE + s)*HSTAGE*2
    auto issue = [&](int chunk, int s) {
        const __half* Ag = A + (size_t)bm * K + chunk * 32;
        const __half* Bg = B + (size_t)bn * K + chunk * 32;
        const uint32_t Ab = sb + s * (HSTAGE * 2);
        const uint32_t Bb = sb + (NSTAGE + s) * (HSTAGE * 2);
#pragma unroll
        for (int j = 0; j < 2; j++) {
            const int row = r0 + j * 64;
            const uint32_t so = (uint32_t)(row * HLD + kc * 8) * 2;
            const __half* ga = Ag + (size_t)row * K + kc * 8;
            const __half* gb = Bg + (size_t)row * K + kc * 8;
            asm volatile("cp.async.cg.shared.global [%0], [%1], 16;" :: "r"(Ab + so), "l"(ga));
            asm volatile("cp.async.cg.shared.global [%0], [%1], 16;" :: "r"(Bb + so), "l"(gb));
        }
    };

    issue(0, 0);
    asm volatile("cp.async.commit_group;" ::: "memory");
    if (nch > 1) issue(1, 1);
    asm volatile("cp.async.commit_group;" ::: "memory");

    const int g = lane >> 2;
    const int t = lane & 3;

    int st = 0;
    for (int i = 0; i < nch; i++) {
        asm volatile("cp.async.wait_group 1;" ::: "memory");
        __syncthreads();

        const __half* Ac = smh + st * HSTAGE;
        const __half* Bc = smh + (NSTAGE + st) * HSTAGE;
#pragma unroll
        for (int kk = 0; kk < 2; kk++) {
            const int kb = kk * 16 + 2 * t;
            uint32_t af[4][4];
#pragma unroll
            for (int mt = 0; mt < 4; mt++) {
                const int mrow = wm * 64 + mt * 16 + g;
                af[mt][0] = *(const uint32_t*)&Ac[(mrow    ) * HLD + kb    ];
                af[mt][1] = *(const uint32_t*)&Ac[(mrow + 8) * HLD + kb    ];
                af[mt][2] = *(const uint32_t*)&Ac[(mrow    ) * HLD + kb + 8];
                af[mt][3] = *(const uint32_t*)&Ac[(mrow + 8) * HLD + kb + 8];
            }
            uint32_t bf[4][2];
#pragma unroll
            for (int nt = 0; nt < 4; nt++) {
                const int nrow = wn * 32 + nt * 8 + g;
                bf[nt][0] = *(const uint32_t*)&Bc[nrow * HLD + kb    ];
                bf[nt][1] = *(const uint32_t*)&Bc[nrow * HLD + kb + 8];
            }
#pragma unroll
            for (int mt = 0; mt < 4; mt++)
#pragma unroll
                for (int nt = 0; nt < 4; nt++)
                    mma_f16(acc[mt][nt], af[mt][0], af[mt][1], af[mt][2], af[mt][3],
                            bf[nt][0], bf[nt][1]);
        }

        __syncthreads();   // all warps done with stage (st+2)%3's future target
        if (i + 2 < nch) issue(i + 2, (st + 2) % NSTAGE);
        asm volatile("cp.async.commit_group;" ::: "memory");
        st = (st + 1) % NSTAGE;
    }

    // epilogue
    const int c2 = t * 2;
#pragma unroll
    for (int mt = 0; mt < 4; mt++) {
#pragma unroll
        for (int nt = 0; nt < 4; nt++) {
            int row = bm + wm * 64 + mt * 16 + g;
            int col = bn + wn * 32 + nt * 8 + c2;
            float v0 = acc[mt][nt][0], v1 = acc[mt][nt][1];
            float v2 = acc[mt][nt][2], v3 = acc[mt][nt][3];
            if (BIAS_RELU) {
                float bb0 = bias[col], bb1 = bias[col + 1];
                v0 = fmaxf(v0 + bb0, 0.0f); v1 = fmaxf(v1 + bb1, 0.0f);
                v2 = fmaxf(v2 + bb0, 0.0f); v3 = fmaxf(v3 + bb1, 0.0f);
            }
            if (OUT_HALF) {
                __half* C = (__half*)Cv;
                *(__half2*)&C[(size_t)row * N + col]       = __floats2half2_rn(v0, v1);
                *(__half2*)&C[(size_t)(row + 8) * N + col] = __floats2half2_rn(v2, v3);
            } else {
                float* C = (float*)Cv;
                *(float2*)&C[(size_t)row * N + col]       = make_float2(v0, v1);
                *(float2*)&C[(size_t)(row + 8) * N + col] = make_float2(v2, v3);
            }
        }
    }
}

// small GEMM: C[NN,10] = A[NN,1024] @ B[1024,10]; W3 staged in smem
__global__ void sgemm_small(const float* __restrict__ A, const float* __restrict__ B,
                            float* __restrict__ C) {
    __shared__ float Ws[H2D * F_OUT];
    int tid = threadIdx.y * F_OUT + threadIdx.x;
    for (int i = tid; i < H2D * F_OUT; i += F_OUT * 16) Ws[i] = B[i];
    __syncthreads();
    int m = blockIdx.x * 16 + threadIdx.y;
    int n = threadIdx.x;
    const float4* a = (const float4*)(A + (size_t)m * H2D);
    float s = 0.0f;
#pragma unroll 8
    for (int k4 = 0; k4 < H2D / 4; k4++) {
        float4 v = a[k4];
        int k = k4 * 4;
        s += v.x * Ws[(k + 0) * F_OUT + n];
        s += v.y * Ws[(k + 1) * F_OUT + n];
        s += v.z * Ws[(k + 2) * F_OUT + n];
        s += v.w * Ws[(k + 3) * F_OUT + n];
    }
    C[m * F_OUT + n] = s;
}

// final: out = log_softmax(a3 + b3)
__global__ void k_logsoftmax(const float* __restrict__ a3, const float* __restrict__ b3,
                             float* __restrict__ out) {
    int m = blockIdx.x * blockDim.x + threadIdx.x;
    if (m >= NN) return;
    float v[F_OUT];
    float mx = -1e30f;
#pragma unroll
    for (int n = 0; n < F_OUT; n++) {
        v[n] = a3[m * F_OUT + n] + b3[n];
        mx = fmaxf(mx, v[n]);
    }
    float s = 0.0f;
#pragma unroll
    for (int n = 0; n < F_OUT; n++) s += expf(v[n] - mx);
    float lse = mx + logf(s);
#pragma unroll
    for (int n = 0; n < F_OUT; n++) out[m * F_OUT + n] = v[n] - lse;
}

// ---------------- launch ----------------
extern "C" void kernel_launch(void* const* d_in, const int* in_sizes, int n_in,
                              void* d_out, int out_size) {
    const float* x  = (const float*)d_in[0];
    const float* W1 = (const float*)d_in[1];
    const float* b1 = (const float*)d_in[2];
    const float* W2 = (const float*)d_in[3];
    const float* b2 = (const float*)d_in[4];
    const float* W3 = (const float*)d_in[5];
    const float* b3 = (const float*)d_in[6];
    const void*  ei = d_in[7];
    float* out = (float*)d_out;

    float *t2, *h2, *t3, *a3;
    __half *aggxh, *w1t, *w2t, *h1h;
    cudaGetSymbolAddress((void**)&aggxh, g_aggxh);
    cudaGetSymbolAddress((void**)&w1t,   g_w1t);
    cudaGetSymbolAddress((void**)&w2t,   g_w2t);
    cudaGetSymbolAddress((void**)&h1h,   g_h1h);
    cudaGetSymbolAddress((void**)&t2,    g_t2);
    cudaGetSymbolAddress((void**)&h2,    g_h2);
    cudaGetSymbolAddress((void**)&t3,    g_t3);
    cudaGetSymbolAddress((void**)&a3,    g_a3);

    cudaFuncSetAttribute(hgemm<true, true>,   cudaFuncAttributeMaxDynamicSharedMemorySize, GEMM_SMEM);
    cudaFuncSetAttribute(hgemm<false, false>, cudaFuncAttributeMaxDynamicSharedMemorySize, GEMM_SMEM);

    // weight transposes (independent of graph preprocessing)
    {
        dim3 blk(32, 8);
        dim3 g1(H1D / 32, F_IN / 32);
        k_transpose_h<<<g1, blk>>>(W1, w1t, F_IN, H1D);
        dim3 g2(H2D / 32, H1D / 32);
        k_transpose_h<<<g2, blk>>>(W2, w2t, H1D, H2D);
    }

    // graph preprocessing: degrees, norms, CSR by destination
    k_detect<<<1, 32>>>(ei);
    k_deg_init<<<(NN + 255) / 256, 256>>>();
    k_deg_count<<<(EE + 255) / 256, 256>>>(ei);
    k_dinv<<<(NN + 255) / 256, 256>>>();
    k_edge_prep<<<(EE + 255) / 256, 256>>>(ei);
    k_scan<<<1, 256>>>();
    k_place<<<(EE + 255) / 256, 256>>>();

    // ---- layer 1: CSR gather (fp32 -> fp16), GEMM + fused bias/relu (fp16 out)
    {
        k_gather1<<<NN, 128>>>(x, aggxh);
        dim3 grid(H1D / 128, NN / 128);
        hgemm<true, true><<<grid, 256, GEMM_SMEM>>>(aggxh, w1t, b1, h1h, NN, H1D, F_IN);
    }

    // ---- layer 2: GEMM (4096 -> 1024), CSR gather + fused bias/relu
    {
        dim3 grid(H2D / 128, NN / 128);
        hgemm<false, false><<<grid, 256, GEMM_SMEM>>>(h1h, w2t, nullptr, t2, NN, H2D, H1D);
        k_gather2<<<NN, 256>>>(t2, b2, h2);
    }

    // ---- layer 3: small GEMM (1024 -> 10), gather, bias + log_softmax
    {
        dim3 blk(F_OUT, 16);
        sgemm_small<<<NN / 16, blk>>>(h2, W3, t3);
        k_gather3<<<(NN * F_OUT + 255) / 256, 256>>>(t3, a3);
        k_logsoftmax<<<(NN + 255) / 256, 256>>>(a3, b3, out);
    }
}